// round 6
// baseline (speedup 1.0000x reference)
#include <cuda_runtime.h>
#include <cuda_fp16.h>
#include <math.h>
#include <stdint.h>

typedef uint32_t u32;

#define MROWS 65536
#define NBLH  4096
#define OUT_ELEMS ((size_t)MROWS * 256)

// Scratch: fp16 pairs packed in u32 words (pairs along the k/d dimension)
__device__ u32 g_qh[(size_t)NBLH * 128 * 16];   // [blq][h][w][dk/2]
__device__ u32 g_kh[(size_t)NBLH * 128 * 16];
__device__ u32 g_vh[(size_t)NBLH * 128 * 16];
__device__ u32 g_attnout[(size_t)MROWS * 128];  // [m][d/2]
__device__ u32 g_wh[4 * 32768];                 // Wq,Wk,Wv,Wfc as fp16 pairs [n][k/2]

// ---------------------------------------------------------------------------
// helpers
// ---------------------------------------------------------------------------
__device__ __forceinline__ u32 f2h2(float lo, float hi) {
    __half2 h = __floats2half2_rn(lo, hi);
    return *reinterpret_cast<u32*>(&h);
}
__device__ __forceinline__ void mma_f16(float* d, const u32* a, u32 b0, u32 b1) {
    asm volatile(
        "mma.sync.aligned.m16n8k16.row.col.f32.f16.f16.f32 "
        "{%0,%1,%2,%3}, {%4,%5,%6,%7}, {%8,%9}, {%0,%1,%2,%3};"
        : "+f"(d[0]), "+f"(d[1]), "+f"(d[2]), "+f"(d[3])
        : "r"(a[0]), "r"(a[1]), "r"(a[2]), "r"(a[3]), "r"(b0), "r"(b1));
}
__device__ __forceinline__ void ldmx4(u32* r, u32 addr) {
    asm volatile("ldmatrix.sync.aligned.m8n8.x4.shared.b16 {%0,%1,%2,%3}, [%4];"
        : "=r"(r[0]), "=r"(r[1]), "=r"(r[2]), "=r"(r[3]) : "r"(addr));
}
__device__ __forceinline__ void ldmx4t(u32* r, u32 addr) {
    asm volatile("ldmatrix.sync.aligned.m8n8.x4.trans.shared.b16 {%0,%1,%2,%3}, [%4];"
        : "=r"(r[0]), "=r"(r[1]), "=r"(r[2]), "=r"(r[3]) : "r"(addr));
}
__device__ __forceinline__ u32 smem_u32(const void* p) {
    u32 a;
    asm("{ .reg .u64 t; cvta.to.shared.u64 t, %1; cvt.u32.u64 %0, t; }" : "=r"(a) : "l"(p));
    return a;
}
__device__ __forceinline__ void cp16(u32 dst, const void* src) {
    asm volatile("cp.async.cg.shared.global [%0], [%1], 16;" :: "r"(dst), "l"(src));
}
__device__ __forceinline__ void st_cs_f2(float* p, float x, float y) {
    asm volatile("st.global.cs.v2.f32 [%0], {%1,%2};" :: "l"(p), "f"(x), "f"(y) : "memory");
}
#define CP_COMMIT() asm volatile("cp.async.commit_group;")
#define CP_WAIT(n)  asm volatile("cp.async.wait_group %0;" :: "n"(n))

// row stride in u32 words for all [row][k] smem tiles (16 data + 4 pad)
#define SW 20

// ---------------------------------------------------------------------------
// Weight pre-conversion to packed fp16
// ---------------------------------------------------------------------------
__global__ void wconv(const float* __restrict__ Wq, const float* __restrict__ Wk,
                      const float* __restrict__ Wv, const float* __restrict__ Wfc)
{
    int i = blockIdx.x * 256 + threadIdx.x;   // 0..32767
    g_wh[i]             = f2h2(Wq[2 * i],  Wq[2 * i + 1]);
    g_wh[32768 + i]     = f2h2(Wk[2 * i],  Wk[2 * i + 1]);
    g_wh[2 * 32768 + i] = f2h2(Wv[2 * i],  Wv[2 * i + 1]);
    g_wh[3 * 32768 + i] = f2h2(Wfc[2 * i], Wfc[2 * i + 1]);
}

// ---------------------------------------------------------------------------
// Kernel A: QKV projection (fp16 mma), 3-stage pipeline, 1 barrier/iter.
// Block 128x128, 8 warps (2x4), warp tile 64x32, BK=32.
// grid (2, 512, 3): x = n-tile (fastest -> consecutive CTAs share X m-tile).
// ---------------------------------------------------------------------------
#define GP_STAGE_W (128 * SW)                       // 2560 words / stage / side
#define GP_SMEM_BYTES (2 * 3 * GP_STAGE_W * 4)      // 61440

__global__ __launch_bounds__(256, 2) void gemm_proj(
    const float* __restrict__ q, const float* __restrict__ k, const float* __restrict__ v,
    const float* __restrict__ bq, const float* __restrict__ bk, const float* __restrict__ bv)
{
    extern __shared__ u32 dyn[];
    u32* As = dyn;                    // [3][128*SW]
    u32* Bs = dyn + 3 * GP_STAGE_W;   // [3][128*SW]

    const int z = blockIdx.z;
    const float* X    = (z == 0) ? q : (z == 1) ? k : v;
    const u32*   Wt   = g_wh + (size_t)z * 32768;
    const float* bias = (z == 0) ? bq : (z == 1) ? bk : bv;
    u32*         outp = (z == 0) ? g_qh : (z == 1) ? g_kh : g_vh;
    const float scale = (z == 0) ? 0.17677669529663687f : 1.0f;

    const int tid  = threadIdx.x;
    const int wid  = tid >> 5;
    const int lane = tid & 31;
    const int g    = lane >> 2;
    const int t    = lane & 3;
    const int lr   = lane & 15;
    const int lc   = (lane >> 4) * 4;
    const int wm   = wid >> 2;    // 0..1
    const int wn   = wid & 3;     // 0..3
    const int m0   = blockIdx.y * 128;
    const int n0   = blockIdx.x * 128;

    const u32 as_b = smem_u32(As);
    const u32 bs_b = smem_u32(Bs);

    const int arow  = tid >> 1;      // A: row, half-row per thread
    const int ahalf = tid & 1;

    // prologue: B chunks 0,1 (cp.async, one group each); A chunks 0,1 direct; A chunk 2 -> fa
    #pragma unroll
    for (int st = 0; st < 2; st++) {
        #pragma unroll
        for (int j = 0; j < 2; j++) {
            int idx = tid + j * 256; int r = idx >> 2, c4 = idx & 3;
            cp16(bs_b + (u32)(st * GP_STAGE_W + r * SW + c4 * 4) * 4,
                 &Wt[(size_t)(n0 + r) * 128 + st * 16 + c4 * 4]);
        }
        CP_COMMIT();
    }
    float4 fa[4];
    #pragma unroll
    for (int st = 0; st < 2; st++) {
        #pragma unroll
        for (int j = 0; j < 4; j++)
            fa[j] = *(const float4*)&X[(size_t)(m0 + arow) * 256 + st * 32 + ahalf * 16 + j * 4];
        u32* dst = &As[st * GP_STAGE_W + arow * SW + ahalf * 8];
        #pragma unroll
        for (int j = 0; j < 4; j++) {
            dst[2 * j]     = f2h2(fa[j].x, fa[j].y);
            dst[2 * j + 1] = f2h2(fa[j].z, fa[j].w);
        }
    }
    #pragma unroll
    for (int j = 0; j < 4; j++)
        fa[j] = *(const float4*)&X[(size_t)(m0 + arow) * 256 + 2 * 32 + ahalf * 16 + j * 4];

    float acc[4][4][4];
    #pragma unroll
    for (int a = 0; a < 4; a++)
        #pragma unroll
        for (int b = 0; b < 4; b++)
            #pragma unroll
            for (int c = 0; c < 4; c++) acc[a][b][c] = 0.0f;

    #pragma unroll 1
    for (int i = 0; i < 8; i++) {
        if (i < 7) { CP_WAIT(1); } else { CP_WAIT(0); }
        __syncthreads();

        // issue loads for chunk i+2 into stage (i+2)%3 (released by this barrier)
        if (i < 6) {
            const int sn = (i + 2) % 3;
            u32* dst = &As[sn * GP_STAGE_W + arow * SW + ahalf * 8];
            #pragma unroll
            for (int j = 0; j < 4; j++) {
                dst[2 * j]     = f2h2(fa[j].x, fa[j].y);
                dst[2 * j + 1] = f2h2(fa[j].z, fa[j].w);
            }
            #pragma unroll
            for (int j = 0; j < 2; j++) {
                int idx = tid + j * 256; int r = idx >> 2, c4 = idx & 3;
                cp16(bs_b + (u32)(sn * GP_STAGE_W + r * SW + c4 * 4) * 4,
                     &Wt[(size_t)(n0 + r) * 128 + (i + 2) * 16 + c4 * 4]);
            }
            CP_COMMIT();
        }
        if (i < 5) {
            #pragma unroll
            for (int j = 0; j < 4; j++)
                fa[j] = *(const float4*)&X[(size_t)(m0 + arow) * 256 + (i + 3) * 32 + ahalf * 16 + j * 4];
        }

        // compute chunk i from stage i%3
        const int s = i % 3;
        const u32 a0 = as_b + (u32)(s * GP_STAGE_W) * 4;
        const u32 b0 = bs_b + (u32)(s * GP_STAGE_W) * 4;
        #pragma unroll
        for (int c = 0; c < 2; c++) {
            u32 ra[4][4];
            #pragma unroll
            for (int mt = 0; mt < 4; mt++)
                ldmx4(ra[mt], a0 + (u32)((wm * 64 + mt * 16 + lr) * SW + c * 8 + lc) * 4);
            #pragma unroll
            for (int qq = 0; qq < 2; qq++) {
                u32 rb[4];
                ldmx4(rb, b0 + (u32)((wn * 32 + qq * 16 + lr) * SW + c * 8 + lc) * 4);
                #pragma unroll
                for (int mt = 0; mt < 4; mt++) {
                    mma_f16(acc[mt][2 * qq],     ra[mt], rb[0], rb[2]);
                    mma_f16(acc[mt][2 * qq + 1], ra[mt], rb[1], rb[3]);
                }
            }
        }
    }

    // epilogue: bias, scale, pack fp16 pairs, scatter to [blq][h][w][dk/2]
    #pragma unroll
    for (int mt = 0; mt < 4; mt++) {
        #pragma unroll
        for (int nt = 0; nt < 4; nt++) {
            int n  = n0 + wn * 32 + nt * 8 + 2 * t;
            int h  = n >> 5;
            int dw = (n & 31) >> 1;
            float b0v = bias[n], b1v = bias[n + 1];
            #pragma unroll
            for (int rs = 0; rs < 2; rs++) {
                int m   = m0 + wm * 64 + mt * 16 + g + 8 * rs;
                int blq = m >> 7;
                int ww  = m & 127;
                outp[(((size_t)blq * 8 + h) * 128 + ww) * 16 + dw] =
                    f2h2((acc[mt][nt][2 * rs]     + b0v) * scale,
                         (acc[mt][nt][2 * rs + 1] + b1v) * scale);
            }
        }
    }
}

// ---------------------------------------------------------------------------
// Kernel B: attention per (b,l,h), fp16 mma + ldmatrix.
// attn probs written with .cs streaming hint (write-once, 268MB).
// ---------------------------------------------------------------------------
__global__ __launch_bounds__(256, 2) void attn_kernel(float* __restrict__ attn_out)
{
    __shared__ u32 Qs[128 * SW];
    __shared__ u32 Ks[128 * SW];
    __shared__ u32 Vs[128 * SW];

    const int blk  = blockIdx.x;
    const int tid  = threadIdx.x;
    const int wid  = tid >> 5;
    const int lane = tid & 31;
    const int g    = lane >> 2;
    const int t    = lane & 3;
    const int lr   = lane & 15;
    const int lc   = (lane >> 4) * 4;

    const u32 qs_b = smem_u32(Qs);
    const u32 ks_b = smem_u32(Ks);
    const u32 vs_b = smem_u32(Vs);

    const uint4* Qg = (const uint4*)(g_qh + (size_t)blk * 2048);
    const uint4* Kg = (const uint4*)(g_kh + (size_t)blk * 2048);
    const uint4* Vg = (const uint4*)(g_vh + (size_t)blk * 2048);

    #pragma unroll
    for (int j = 0; j < 2; j++) {
        int idx = tid + j * 256;
        int row = idx >> 2, q4 = idx & 3;
        *(uint4*)&Qs[row * SW + q4 * 4] = Qg[idx];
        *(uint4*)&Ks[row * SW + q4 * 4] = Kg[idx];
        *(uint4*)&Vs[row * SW + q4 * 4] = Vg[idx];
    }
    __syncthreads();

    // S = Q K^T : 16 rows x 128 cols per warp
    float sacc[16][4];
    #pragma unroll
    for (int nt = 0; nt < 16; nt++)
        #pragma unroll
        for (int c = 0; c < 4; c++) sacc[nt][c] = 0.0f;

    const int rbase16 = wid * 16;
    const int rbase   = rbase16 + g;
    #pragma unroll
    for (int c = 0; c < 2; c++) {
        u32 ra[4];
        ldmx4(ra, qs_b + (u32)((rbase16 + lr) * SW + c * 8 + lc) * 4);
        #pragma unroll
        for (int qq = 0; qq < 8; qq++) {
            u32 rb[4];
            ldmx4(rb, ks_b + (u32)((qq * 16 + lr) * SW + c * 8 + lc) * 4);
            mma_f16(sacc[2 * qq],     ra, rb[0], rb[2]);
            mma_f16(sacc[2 * qq + 1], ra, rb[1], rb[3]);
        }
    }

    // softmax (rows shared within lane quads via xor 1,2)
    float inv[2];
    #pragma unroll
    for (int rs = 0; rs < 2; rs++) {
        float mx = -1e30f;
        #pragma unroll
        for (int nt = 0; nt < 16; nt++) {
            mx = fmaxf(mx, sacc[nt][2 * rs]);
            mx = fmaxf(mx, sacc[nt][2 * rs + 1]);
        }
        mx = fmaxf(mx, __shfl_xor_sync(0xffffffffu, mx, 1));
        mx = fmaxf(mx, __shfl_xor_sync(0xffffffffu, mx, 2));
        float s = 0.0f;
        #pragma unroll
        for (int nt = 0; nt < 16; nt++) {
            float e0 = __expf(sacc[nt][2 * rs] - mx);
            float e1 = __expf(sacc[nt][2 * rs + 1] - mx);
            sacc[nt][2 * rs] = e0; sacc[nt][2 * rs + 1] = e1;
            s += e0 + e1;
        }
        s += __shfl_xor_sync(0xffffffffu, s, 1);
        s += __shfl_xor_sync(0xffffffffu, s, 2);
        inv[rs] = 1.0f / s;
    }
    #pragma unroll
    for (int nt = 0; nt < 16; nt++) {
        sacc[nt][0] *= inv[0]; sacc[nt][1] *= inv[0];
        sacc[nt][2] *= inv[1]; sacc[nt][3] *= inv[1];
    }

    // write attn probs (fp32, streaming)
    const size_t abase = (size_t)blk * 16384;
    #pragma unroll
    for (int nt = 0; nt < 16; nt++) {
        int col = nt * 8 + 2 * t;
        st_cs_f2(&attn_out[abase + (size_t)rbase * 128 + col],       sacc[nt][0], sacc[nt][1]);
        st_cs_f2(&attn_out[abase + (size_t)(rbase + 8) * 128 + col], sacc[nt][2], sacc[nt][3]);
    }

    // O = P V : A-frags packed from sacc; B via ldmatrix.trans on Vs[j][d]
    float oacc[4][4];
    #pragma unroll
    for (int nt = 0; nt < 4; nt++)
        #pragma unroll
        for (int c = 0; c < 4; c++) oacc[nt][c] = 0.0f;

    const int vrow_off = ((lane >> 3) & 1) * 8 + (lane & 7);
    const int vcol_off = (lane >> 4) * 4;
    #pragma unroll
    for (int ks = 0; ks < 8; ks++) {
        u32 af[4];
        af[0] = f2h2(sacc[2 * ks][0],     sacc[2 * ks][1]);
        af[1] = f2h2(sacc[2 * ks][2],     sacc[2 * ks][3]);
        af[2] = f2h2(sacc[2 * ks + 1][0], sacc[2 * ks + 1][1]);
        af[3] = f2h2(sacc[2 * ks + 1][2], sacc[2 * ks + 1][3]);
        #pragma unroll
        for (int np = 0; np < 2; np++) {
            u32 rb[4];
            ldmx4t(rb, vs_b + (u32)((16 * ks + vrow_off) * SW + np * 8 + vcol_off) * 4);
            mma_f16(oacc[2 * np],     af, rb[0], rb[1]);
            mma_f16(oacc[2 * np + 1], af, rb[2], rb[3]);
        }
    }

    // store O as fp16 pairs to [m][d/2]
    const int blq = blk >> 3;
    const int h   = blk & 7;
    #pragma unroll
    for (int nt = 0; nt < 4; nt++) {
        #pragma unroll
        for (int rs = 0; rs < 2; rs++) {
            int m = blq * 128 + rbase + 8 * rs;
            g_attnout[(size_t)m * 128 + h * 16 + nt * 4 + t] =
                f2h2(oacc[nt][2 * rs], oacc[nt][2 * rs + 1]);
        }
    }
}

// ---------------------------------------------------------------------------
// Kernel C: FC + residual + LayerNorm, 3-stage cp.async, 1 barrier/iter.
// Block 128x256, 512 threads (16 warps 4x4), warp tile 32x64.
// ---------------------------------------------------------------------------
#define FC_A_STAGE_W (128 * SW)    // 2560
#define FC_B_STAGE_W (256 * SW)    // 5120
#define FC_AS_W (3 * FC_A_STAGE_W)
#define FC_BS_W (3 * FC_B_STAGE_W)
#define FC_SMEM_BYTES ((FC_AS_W + FC_BS_W + 1024) * 4)   // 96256

__global__ __launch_bounds__(512, 1) void fc_ln_kernel(
    const float* __restrict__ bfc, const float* __restrict__ resid,
    const float* __restrict__ ln_w, const float* __restrict__ ln_b,
    float* __restrict__ out)
{
    extern __shared__ u32 dyn[];
    u32*  As  = dyn;
    u32*  Bs  = dyn + FC_AS_W;
    float* red = (float*)(dyn + FC_AS_W + FC_BS_W);   // [128][8]

    const u32* Wt = g_wh + 3 * 32768;
    const int tid  = threadIdx.x;
    const int wid  = tid >> 5;
    const int lane = tid & 31;
    const int g    = lane >> 2;
    const int t    = lane & 3;
    const int lr   = lane & 15;
    const int lc   = (lane >> 4) * 4;
    const int wm   = wid >> 2;   // 0..3
    const int wn   = wid & 3;    // 0..3
    const size_t m0 = (size_t)blockIdx.x * 128;

    const u32 as_b = smem_u32(As);
    const u32 bs_b = smem_u32(Bs);

    // prologue: stages 0,1 (one commit group per chunk, A+B together)
    #pragma unroll
    for (int st = 0; st < 2; st++) {
        {
            int r = tid >> 2, c4 = tid & 3;   // A: 512 chunks
            cp16(as_b + (u32)(st * FC_A_STAGE_W + r * SW + c4 * 4) * 4,
                 &g_attnout[(m0 + r) * 128 + st * 16 + c4 * 4]);
        }
        #pragma unroll
        for (int j = 0; j < 2; j++) {         // B: 1024 chunks
            int idx = tid + j * 512; int r = idx >> 2, c4 = idx & 3;
            cp16(bs_b + (u32)(st * FC_B_STAGE_W + r * SW + c4 * 4) * 4,
                 &Wt[(size_t)r * 128 + st * 16 + c4 * 4]);
        }
        CP_COMMIT();
    }

    float acc[2][8][4];
    #pragma unroll
    for (int a = 0; a < 2; a++)
        #pragma unroll
        for (int b = 0; b < 8; b++)
            #pragma unroll
            for (int c = 0; c < 4; c++) acc[a][b][c] = 0.0f;

    #pragma unroll 1
    for (int i = 0; i < 8; i++) {
        if (i < 7) { CP_WAIT(1); } else { CP_WAIT(0); }
        __syncthreads();

        if (i < 6) {
            const int sn = (i + 2) % 3;
            {
                int r = tid >> 2, c4 = tid & 3;
                cp16(as_b + (u32)(sn * FC_A_STAGE_W + r * SW + c4 * 4) * 4,
                     &g_attnout[(m0 + r) * 128 + (i + 2) * 16 + c4 * 4]);
            }
            #pragma unroll
            for (int j = 0; j < 2; j++) {
                int idx = tid + j * 512; int r = idx >> 2, c4 = idx & 3;
                cp16(bs_b + (u32)(sn * FC_B_STAGE_W + r * SW + c4 * 4) * 4,
                     &Wt[(size_t)r * 128 + (i + 2) * 16 + c4 * 4]);
            }
            CP_COMMIT();
        }

        const int s = i % 3;
        const u32 a0 = as_b + (u32)(s * FC_A_STAGE_W) * 4;
        const u32 b0 = bs_b + (u32)(s * FC_B_STAGE_W) * 4;
        #pragma unroll
        for (int c = 0; c < 2; c++) {
            u32 ra[2][4];
            #pragma unroll
            for (int mt = 0; mt < 2; mt++)
                ldmx4(ra[mt], a0 + (u32)((wm * 32 + mt * 16 + lr) * SW + c * 8 + lc) * 4);
            #pragma unroll
            for (int qq = 0; qq < 4; qq++) {
                u32 rb[4];
                ldmx4(rb, b0 + (u32)((wn * 64 + qq * 16 + lr) * SW + c * 8 + lc) * 4);
                #pragma unroll
                for (int mt = 0; mt < 2; mt++) {
                    mma_f16(acc[mt][2 * qq],     ra[mt], rb[0], rb[2]);
                    mma_f16(acc[mt][2 * qq + 1], ra[mt], rb[1], rb[3]);
                }
            }
        }
    }

    // bias + residual + row stats
    #pragma unroll
    for (int mt = 0; mt < 2; mt++) {
        #pragma unroll
        for (int rs = 0; rs < 2; rs++) {
            int rloc = wm * 32 + mt * 16 + g + 8 * rs;
            float s = 0.0f, sq = 0.0f;
            #pragma unroll
            for (int nt = 0; nt < 8; nt++) {
                int col = wn * 64 + nt * 8 + 2 * t;
                float2 rr = *(const float2*)&resid[(m0 + rloc) * 256 + col];
                float v0 = acc[mt][nt][2 * rs]     + bfc[col]     + rr.x;
                float v1 = acc[mt][nt][2 * rs + 1] + bfc[col + 1] + rr.y;
                acc[mt][nt][2 * rs]     = v0;
                acc[mt][nt][2 * rs + 1] = v1;
                s  += v0 + v1;
                sq += v0 * v0 + v1 * v1;
            }
            s  += __shfl_xor_sync(0xffffffffu, s, 1);
            s  += __shfl_xor_sync(0xffffffffu, s, 2);
            sq += __shfl_xor_sync(0xffffffffu, sq, 1);
            sq += __shfl_xor_sync(0xffffffffu, sq, 2);
            if (t == 0) {
                red[rloc * 8 + wn]     = s;
                red[rloc * 8 + 4 + wn] = sq;
            }
        }
    }
    __syncthreads();

    #pragma unroll
    for (int mt = 0; mt < 2; mt++) {
        #pragma unroll
        for (int rs = 0; rs < 2; rs++) {
            int rloc = wm * 32 + mt * 16 + g + 8 * rs;
            float s  = red[rloc * 8 + 0] + red[rloc * 8 + 1] + red[rloc * 8 + 2] + red[rloc * 8 + 3];
            float sq = red[rloc * 8 + 4] + red[rloc * 8 + 5] + red[rloc * 8 + 6] + red[rloc * 8 + 7];
            float mu   = s * (1.0f / 256.0f);
            float var  = sq * (1.0f / 256.0f) - mu * mu;
            float rstd = rsqrtf(var + 1e-6f);
            #pragma unroll
            for (int nt = 0; nt < 8; nt++) {
                int col = wn * 64 + nt * 8 + 2 * t;
                float2 lw = *(const float2*)&ln_w[col];
                float2 lb = *(const float2*)&ln_b[col];
                float2 o;
                o.x = (acc[mt][nt][2 * rs]     - mu) * rstd * lw.x + lb.x;
                o.y = (acc[mt][nt][2 * rs + 1] - mu) * rstd * lw.y + lb.y;
                *(float2*)&out[(m0 + rloc) * 256 + col] = o;
            }
        }
    }
}

// ---------------------------------------------------------------------------
extern "C" void kernel_launch(void* const* d_in, const int* in_sizes, int n_in,
                              void* d_out, int out_size)
{
    const float* q    = (const float*)d_in[0];
    const float* k    = (const float*)d_in[1];
    const float* v    = (const float*)d_in[2];
    const float* Wq   = (const float*)d_in[3];
    const float* bq   = (const float*)d_in[4];
    const float* Wk   = (const float*)d_in[5];
    const float* bk   = (const float*)d_in[6];
    const float* Wv   = (const float*)d_in[7];
    const float* bv   = (const float*)d_in[8];
    const float* Wfc  = (const float*)d_in[9];
    const float* bfc  = (const float*)d_in[10];
    const float* ln_w = (const float*)d_in[11];
    const float* ln_b = (const float*)d_in[12];

    float* out  = (float*)d_out;
    float* attn = out + OUT_ELEMS;

    static bool attr_set = false;
    if (!attr_set) {
        cudaFuncSetAttribute(gemm_proj,    cudaFuncAttributeMaxDynamicSharedMemorySize, GP_SMEM_BYTES);
        cudaFuncSetAttribute(fc_ln_kernel, cudaFuncAttributeMaxDynamicSharedMemorySize, FC_SMEM_BYTES);
        attr_set = true;
    }

    wconv<<<128, 256>>>(Wq, Wk, Wv, Wfc);
    gemm_proj<<<dim3(2, 512, 3), 256, GP_SMEM_BYTES>>>(q, k, v, bq, bk, bv);
    attn_kernel<<<NBLH, 256>>>(attn);
    fc_ln_kernel<<<512, 512, FC_SMEM_BYTES>>>(bfc, q, ln_w, ln_b, out);
}